// round 3
// baseline (speedup 1.0000x reference)
#include <cuda_runtime.h>
#include <cuda_bf16.h>

// LinkPredictorMLP: out[e] = thresh(relu( relu([emb[row];emb[col]] @ W1 + b1) @ W2 + b2 ))
// E = 600000, D = 128, H = 256, N = 100000.
//
// Round-2: same fp32 SIMT GEMM tiling as round-1; FIX: edge_index is int32
// (JAX x64 is disabled -> jnp.int64 request silently yields int32).
// - 64 edges per CTA, 128 threads, H processed in 2 chunks of 128.
// - x tile (64 x 256 fp32) and W1 chunk (256 x 128 fp32) staged in shared memory.
// - 8x8 register tile per thread -> 12 LDS.128 per 256 FMA (LDS not the bottleneck).
// - raw never materializes h: per-chunk relu + dot with W2, accumulated via smem atomics.

#define D        128
#define TWO_D    256
#define H        256
#define BE       64          // edges per block
#define HC       128         // h chunk
#define NCHUNK   (H / HC)    // 2
#define THREADS  128
#define XS_STRIDE 260        // 256 + 4 pad: consecutive rows hit distinct bank quads
#define T_SMALL  0.05f

struct Smem {
    float xs[BE][XS_STRIDE];   // 66,560 B  : concat embeddings, fp32
    float ws[TWO_D][HC];       // 131,072 B : W1 chunk, [k][j]
    float raw[BE];             // per-edge accumulator
    int   nidx[2 * BE];        // gathered node ids (row/col interleaved)
};

__global__ __launch_bounds__(THREADS, 1)
void edge_mlp_kernel(const float* __restrict__ emb,
                     const int* __restrict__ eidx,
                     const float* __restrict__ W1,
                     const float* __restrict__ b1,
                     const float* __restrict__ W2,
                     const float* __restrict__ b2,
                     float* __restrict__ out,
                     int E)
{
    extern __shared__ char smem_raw[];
    Smem& s = *reinterpret_cast<Smem*>(smem_raw);

    const int t = threadIdx.x;
    const int e_base = blockIdx.x * BE;

    // ---- load node indices for this block's edges ----
    if (t < 2 * BE) {
        int e    = t >> 1;          // local edge
        int side = t & 1;           // 0 = row, 1 = col
        int eg   = e_base + e;
        if (eg >= E) eg = E - 1;    // clamp (defensive; E divisible by BE here)
        s.nidx[t] = eidx[side * E + eg];
    }
    if (t < BE) s.raw[t] = 0.0f;
    __syncthreads();

    // ---- gather embeddings into xs: xs[e][0:128)=emb[row], xs[e][128:256)=emb[col] ----
    // 128 logical rows (edge,side) x 32 float4 columns.
    {
        #pragma unroll 8
        for (int it = 0; it < 32; ++it) {
            int idx = t + THREADS * it;      // 0 .. 4095
            int r   = idx >> 5;              // 0 .. 127  (edge*2 + side)
            int c   = idx & 31;              // float4 column 0..31
            int e   = r >> 1;
            int side = r & 1;
            int node = s.nidx[r];
            float4 v = *reinterpret_cast<const float4*>(emb + (long long)node * D + c * 4);
            *reinterpret_cast<float4*>(&s.xs[e][side * D + c * 4]) = v;
        }
    }
    __syncthreads();

    const int eg = t & 7;          // edge group 0..7   (edges eg + 8*i)
    const int jg = t >> 3;         // h group    0..15  (h = j0 .. j0+7)
    const int j0 = jg * 8;

    const float b2v = b2[0];

    for (int chunk = 0; chunk < NCHUNK; ++chunk) {
        // ---- stage W1 chunk: ws[k][j] = W1[k][chunk*HC + j], 256 rows x 32 float4 ----
        {
            const float* w1c = W1 + chunk * HC;
            #pragma unroll 8
            for (int it = 0; it < 64; ++it) {
                int idx = t + THREADS * it;      // 0 .. 8191
                int k   = idx >> 5;              // 0 .. 255
                int c   = idx & 31;              // float4 col
                float4 v = *reinterpret_cast<const float4*>(w1c + (long long)k * H + c * 4);
                *reinterpret_cast<float4*>(&s.ws[k][c * 4]) = v;
            }
        }
        __syncthreads();

        // ---- 8 edges x 8 h per thread, k in steps of 4 ----
        float acc[8][8];
        #pragma unroll
        for (int i = 0; i < 8; ++i)
            #pragma unroll
            for (int j = 0; j < 8; ++j) acc[i][j] = 0.0f;

        #pragma unroll 2
        for (int k = 0; k < TWO_D; k += 4) {
            float wk[4][8];
            #pragma unroll
            for (int kk = 0; kk < 4; ++kk) {
                float4 a  = *reinterpret_cast<const float4*>(&s.ws[k + kk][j0]);
                float4 bq = *reinterpret_cast<const float4*>(&s.ws[k + kk][j0 + 4]);
                wk[kk][0] = a.x;  wk[kk][1] = a.y;  wk[kk][2] = a.z;  wk[kk][3] = a.w;
                wk[kk][4] = bq.x; wk[kk][5] = bq.y; wk[kk][6] = bq.z; wk[kk][7] = bq.w;
            }
            #pragma unroll
            for (int i = 0; i < 8; ++i) {
                float4 xv = *reinterpret_cast<const float4*>(&s.xs[eg + 8 * i][k]);
                float xk[4] = {xv.x, xv.y, xv.z, xv.w};
                #pragma unroll
                for (int kk = 0; kk < 4; ++kk)
                    #pragma unroll
                    for (int j = 0; j < 8; ++j)
                        acc[i][j] = fmaf(xk[kk], wk[kk][j], acc[i][j]);
            }
        }

        // ---- epilogue: relu(h + b1) dot W2-slice, accumulate raw ----
        {
            const int hb = chunk * HC + j0;
            float b1r[8], w2r[8];
            #pragma unroll
            for (int j = 0; j < 8; ++j) { b1r[j] = b1[hb + j]; w2r[j] = W2[hb + j]; }
            #pragma unroll
            for (int i = 0; i < 8; ++i) {
                float p = 0.0f;
                #pragma unroll
                for (int j = 0; j < 8; ++j) {
                    float hv = fmaxf(acc[i][j] + b1r[j], 0.0f);
                    p = fmaf(hv, w2r[j], p);
                }
                atomicAdd(&s.raw[eg + 8 * i], p);
            }
        }
        __syncthreads();   // raw complete for this chunk; ws safe to overwrite
    }

    // ---- finalize ----
    if (t < BE) {
        int e = e_base + t;
        if (e < E) {
            float v = s.raw[t] + b2v;
            v = fmaxf(v, 0.0f);
            out[e] = (v < T_SMALL) ? 0.0f : v;
        }
    }
}

extern "C" void kernel_launch(void* const* d_in, const int* in_sizes, int n_in,
                              void* d_out, int out_size)
{
    const float* emb  = (const float*)d_in[0];
    const int*   eidx = (const int*)d_in[1];     // int32! (JAX x64 disabled)
    const float* W1   = (const float*)d_in[2];
    const float* b1   = (const float*)d_in[3];
    const float* W2   = (const float*)d_in[4];
    const float* b2   = (const float*)d_in[5];
    float*       out  = (float*)d_out;

    const int E = in_sizes[1] / 2;   // edge_index has 2*E int32 elements
    const int smem_bytes = (int)sizeof(Smem);

    cudaFuncSetAttribute(edge_mlp_kernel,
                         cudaFuncAttributeMaxDynamicSharedMemorySize, smem_bytes);

    const int grid = (E + BE - 1) / BE;
    edge_mlp_kernel<<<grid, THREADS, smem_bytes>>>(emb, eidx, W1, b1, W2, b2, out, E);
}

// round 5
// speedup vs baseline: 2.2173x; 2.2173x over previous
#include <cuda_runtime.h>
#include <cuda_bf16.h>
#include <cstdint>

// LinkPredictorMLP via warp-level HMMA (mma.sync m16n8k16 bf16) — sm_103-safe PTX.
// out[e] = thresh(relu( relu([emb[row];emb[col]] @ W1 + b1) @ W2 + b2 ))
// E = 600000, D = 128 (K=256 concat), H = 256, N = 100000.
//
// bf16 split precision: v = hi + lo (two bf16). acc += Ah*Bh + Ah*Bl + Al*Bh (fp32 accum),
// dropping lo*lo -> rel err ~1e-5.
//
// Persistent: 148 CTAs = 74 tile-groups x 2 H-halves. CTA = 256 thr (8 warps, 4Mx2N),
// tile = 128 edges x 128 h-cols. W1^T-half (hi/lo bf16) resident in smem; X gathered
// per K-chunk of 128 (one endpoint side), split hi/lo on the fly. Epilogue in registers:
// relu(+b1) dot W2, quad shfl reduce, atomicAdd into g_raw; finalize adds b2+relu+thresh.

#define T_SMALL  0.05f
#define MAX_E    600064
__device__ float g_raw[MAX_E];

#define THREADS   256
#define XS_STRIDE 136   // bf16 per X row (128 + 8 pad): 272B = 68 words, 68%32=4 -> ldmatrix conflict-free
#define WS_STRIDE 264   // bf16 per W row (256 + 8 pad): 528B = 132 words, 132%32=4 -> conflict-free

// smem byte offsets
#define SM_XH    0                              // 128*136*2 = 34816
#define SM_XL    34816                          // 34816
#define SM_WH    69632                          // 128*264*2 = 67584
#define SM_WL    137216                         // 67584
#define SM_B1    204800                         // 512
#define SM_W2    205312                         // 512
#define SM_NIDX  205824                         // 1024
#define SM_TOTAL 206848

__device__ __forceinline__ uint32_t smem_u32(const void* p) {
    uint32_t a;
    asm("{ .reg .u64 t; cvta.to.shared.u64 t, %1; cvt.u32.u64 %0, t; }" : "=r"(a) : "l"(p));
    return a;
}
__device__ __forceinline__ void ldmx4(uint32_t* r, uint32_t addr) {
    asm volatile("ldmatrix.sync.aligned.m8n8.x4.shared.b16 {%0,%1,%2,%3}, [%4];"
                 : "=r"(r[0]), "=r"(r[1]), "=r"(r[2]), "=r"(r[3]) : "r"(addr));
}
__device__ __forceinline__ void mma16816(float* c, const uint32_t* a, const uint32_t* b) {
    asm volatile("mma.sync.aligned.m16n8k16.row.col.f32.bf16.bf16.f32 "
                 "{%0,%1,%2,%3}, {%4,%5,%6,%7}, {%8,%9}, {%0,%1,%2,%3};"
                 : "+f"(c[0]), "+f"(c[1]), "+f"(c[2]), "+f"(c[3])
                 : "r"(a[0]), "r"(a[1]), "r"(a[2]), "r"(a[3]), "r"(b[0]), "r"(b[1]));
}
__device__ __forceinline__ uint32_t pk(__nv_bfloat162 v) { return *reinterpret_cast<uint32_t*>(&v); }

__global__ __launch_bounds__(THREADS, 1)
void edge_mlp_hmma(const float* __restrict__ emb,
                   const int*   __restrict__ eidx,
                   const float* __restrict__ W1,
                   const float* __restrict__ b1,
                   const float* __restrict__ W2,
                   int E, int ntiles)
{
    extern __shared__ char smem[];
    const uint32_t sbase = smem_u32(smem);

    __nv_bfloat16* xh  = reinterpret_cast<__nv_bfloat16*>(smem + SM_XH);
    __nv_bfloat16* xl  = reinterpret_cast<__nv_bfloat16*>(smem + SM_XL);
    __nv_bfloat16* wh  = reinterpret_cast<__nv_bfloat16*>(smem + SM_WH);
    __nv_bfloat16* wl  = reinterpret_cast<__nv_bfloat16*>(smem + SM_WL);
    float* b1s = reinterpret_cast<float*>(smem + SM_B1);
    float* w2s = reinterpret_cast<float*>(smem + SM_W2);
    int*  nidx = reinterpret_cast<int*>(smem + SM_NIDX);

    const int t    = threadIdx.x;
    const int lane = t & 31;
    const int wid  = t >> 5;
    const int wm   = wid & 3;     // M block: rows wm*32 .. +31
    const int wn   = wid >> 2;    // N block: cols wn*64 .. +63

    const int halfId   = blockIdx.x & 1;
    const int group    = blockIdx.x >> 1;       // 0..73
    const int halfBase = halfId * 128;

    if (t < 128) { b1s[t] = b1[halfBase + t]; w2s[t] = W2[halfBase + t]; }

    // ---- resident W1^T half, hi/lo split: wh/wl[n][k], n=0..127 local, k=0..255 ----
    #pragma unroll 4
    for (int i = 0; i < 128; ++i) {
        int idx = t + THREADS * i;     // 0..32767
        int k = idx >> 7;              // 0..255  (coalesced over n)
        int n = idx & 127;
        float w = W1[k * 256 + halfBase + n];
        __nv_bfloat16 h = __float2bfloat16_rn(w);
        __nv_bfloat16 l = __float2bfloat16_rn(w - __bfloat162float(h));
        wh[n * WS_STRIDE + k] = h;
        wl[n * WS_STRIDE + k] = l;
    }
    __syncthreads();

    for (int tile = group; tile < ntiles; tile += 74) {
        // ---- edge indices ----
        {
            int side = t >> 7, r = t & 127;
            int e = tile * 128 + r;
            if (e >= E) e = E - 1;
            nidx[side * 128 + r] = eidx[side * E + e];
        }
        __syncthreads();

        float acc[2][8][4];
        #pragma unroll
        for (int mi = 0; mi < 2; ++mi)
            #pragma unroll
            for (int nf = 0; nf < 8; ++nf)
                #pragma unroll
                for (int p = 0; p < 4; ++p) acc[mi][nf][p] = 0.0f;

        #pragma unroll
        for (int chunk = 0; chunk < 2; ++chunk) {
            // ---- gather side=chunk into xh/xl (128 rows x 128 dims) ----
            {
                int r      = t & 127;       // row (conflict-free STS phases)
                int half64 = t >> 7;        // which 64 dims
                int node   = nidx[chunk * 128 + r];
                const float4* src = reinterpret_cast<const float4*>(
                    emb + (size_t)node * 128 + half64 * 64);
                __nv_bfloat16* dh = xh + r * XS_STRIDE + half64 * 64;
                __nv_bfloat16* dl = xl + r * XS_STRIDE + half64 * 64;
                #pragma unroll
                for (int q = 0; q < 8; ++q) {
                    float4 v0 = src[2 * q], v1 = src[2 * q + 1];
                    __nv_bfloat162 h01 = __floats2bfloat162_rn(v0.x, v0.y);
                    __nv_bfloat162 h23 = __floats2bfloat162_rn(v0.z, v0.w);
                    __nv_bfloat162 h45 = __floats2bfloat162_rn(v1.x, v1.y);
                    __nv_bfloat162 h67 = __floats2bfloat162_rn(v1.z, v1.w);
                    __nv_bfloat162 l01 = __floats2bfloat162_rn(v0.x - __bfloat162float(h01.x),
                                                               v0.y - __bfloat162float(h01.y));
                    __nv_bfloat162 l23 = __floats2bfloat162_rn(v0.z - __bfloat162float(h23.x),
                                                               v0.w - __bfloat162float(h23.y));
                    __nv_bfloat162 l45 = __floats2bfloat162_rn(v1.x - __bfloat162float(h45.x),
                                                               v1.y - __bfloat162float(h45.y));
                    __nv_bfloat162 l67 = __floats2bfloat162_rn(v1.z - __bfloat162float(h67.x),
                                                               v1.w - __bfloat162float(h67.y));
                    *reinterpret_cast<uint4*>(dh + q * 8) = make_uint4(pk(h01), pk(h23), pk(h45), pk(h67));
                    *reinterpret_cast<uint4*>(dl + q * 8) = make_uint4(pk(l01), pk(l23), pk(l45), pk(l67));
                }
            }
            __syncthreads();

            // ---- 8 ksteps of m16n8k16 ----
            #pragma unroll
            for (int ks = 0; ks < 8; ++ks) {
                const int kl = ks * 16;            // local k in X
                const int kg = chunk * 128 + kl;   // global k in W

                uint32_t Ah[2][4], Al[2][4];
                #pragma unroll
                for (int mi = 0; mi < 2; ++mi) {
                    int row  = wm * 32 + mi * 16 + (lane & 15);
                    int koff = kl + ((lane >> 4) << 3);
                    uint32_t a = sbase + SM_XH + (uint32_t)(row * XS_STRIDE + koff) * 2;
                    ldmx4(Ah[mi], a);
                    ldmx4(Al[mi], a + (SM_XL - SM_XH));
                }
                uint32_t Bh[8][2], Bl[8][2];
                #pragma unroll
                for (int np = 0; np < 4; ++np) {
                    int nrow = wn * 64 + np * 16 + (lane & 15);
                    int koff = kg + ((lane >> 4) << 3);
                    uint32_t a = sbase + SM_WH + (uint32_t)(nrow * WS_STRIDE + koff) * 2;
                    uint32_t r4[4];
                    ldmx4(r4, a);
                    Bh[2*np][0] = r4[0]; Bh[2*np+1][0] = r4[1];
                    Bh[2*np][1] = r4[2]; Bh[2*np+1][1] = r4[3];
                    ldmx4(r4, a + (SM_WL - SM_WH));
                    Bl[2*np][0] = r4[0]; Bl[2*np+1][0] = r4[1];
                    Bl[2*np][1] = r4[2]; Bl[2*np+1][1] = r4[3];
                }
                #pragma unroll
                for (int mi = 0; mi < 2; ++mi)
                    #pragma unroll
                    for (int nf = 0; nf < 8; ++nf) {
                        mma16816(acc[mi][nf], Ah[mi], Bh[nf]);
                        mma16816(acc[mi][nf], Ah[mi], Bl[nf]);
                        mma16816(acc[mi][nf], Al[mi], Bh[nf]);
                    }
            }
            __syncthreads();   // X consumed; safe to regather next chunk
        }

        // ---- epilogue: relu(+b1) dot W2 over this warp's 64 cols ----
        #pragma unroll
        for (int mi = 0; mi < 2; ++mi) {
            float p0 = 0.0f, p1 = 0.0f;
            #pragma unroll
            for (int nf = 0; nf < 8; ++nf) {
                int c0 = wn * 64 + nf * 8 + 2 * (lane & 3);
                float bi0 = b1s[c0], bi1 = b1s[c0 + 1];
                float wv0 = w2s[c0], wv1 = w2s[c0 + 1];
                p0 = fmaf(fmaxf(acc[mi][nf][0] + bi0, 0.0f), wv0, p0);
                p0 = fmaf(fmaxf(acc[mi][nf][1] + bi1, 0.0f), wv1, p0);
                p1 = fmaf(fmaxf(acc[mi][nf][2] + bi0, 0.0f), wv0, p1);
                p1 = fmaf(fmaxf(acc[mi][nf][3] + bi1, 0.0f), wv1, p1);
            }
            p0 += __shfl_xor_sync(0xffffffffu, p0, 1);
            p0 += __shfl_xor_sync(0xffffffffu, p0, 2);
            p1 += __shfl_xor_sync(0xffffffffu, p1, 1);
            p1 += __shfl_xor_sync(0xffffffffu, p1, 2);
            if ((lane & 3) == 0) {
                int r0 = wm * 32 + mi * 16 + (lane >> 2);
                int e0 = tile * 128 + r0;
                if (e0 < E) atomicAdd(&g_raw[e0], p0);
                if (e0 + 8 < E) atomicAdd(&g_raw[e0 + 8], p1);
            }
        }
        __syncthreads();   // epilogue reads acc only, but keep warps in lockstep before nidx overwrite
    }
}

__global__ void zero_raw(int E) {
    int i = blockIdx.x * blockDim.x + threadIdx.x;
    if (i < E) g_raw[i] = 0.0f;
}

__global__ void finalize(float* __restrict__ out, const float* __restrict__ b2, int E) {
    int i = blockIdx.x * blockDim.x + threadIdx.x;
    if (i < E) {
        float v = fmaxf(g_raw[i] + b2[0], 0.0f);
        out[i] = (v < T_SMALL) ? 0.0f : v;
    }
}

extern "C" void kernel_launch(void* const* d_in, const int* in_sizes, int n_in,
                              void* d_out, int out_size)
{
    const float* emb  = (const float*)d_in[0];
    const int*   eidx = (const int*)d_in[1];     // int32 (JAX x64 disabled)
    const float* W1   = (const float*)d_in[2];
    const float* b1   = (const float*)d_in[3];
    const float* W2   = (const float*)d_in[4];
    const float* b2   = (const float*)d_in[5];
    float*       out  = (float*)d_out;

    const int E = in_sizes[1] / 2;
    const int ntiles = (E + 127) / 128;

    cudaFuncSetAttribute(edge_mlp_hmma, cudaFuncAttributeMaxDynamicSharedMemorySize, SM_TOTAL);

    zero_raw<<<(E + 255) / 256, 256>>>(E);
    edge_mlp_hmma<<<148, THREADS, SM_TOTAL>>>(emb, eidx, W1, b1, W2, E, ntiles);
    finalize<<<(E + 255) / 256, 256>>>(out, b2, E);
}

// round 7
// speedup vs baseline: 2.8976x; 1.3068x over previous
#include <cuda_runtime.h>
#include <cuda_bf16.h>
#include <cstdint>

// LinkPredictorMLP via warp-level HMMA (mma.sync m16n8k16 bf16) — sm_103-safe PTX.
// out[e] = thresh(relu( relu([emb[row];emb[col]] @ W1 + b1) @ W2 + b2 ))
// E = 600000, D = 128 (K=256 concat), H = 256, N = 100000.
//
// Round-5: 512 threads (16 warps, 4Mx4N grid, 32x32 warp tiles) + register-prefetch
// pipeline: LDGs for the next K-chunk (incl. edge-index load) issued before the MMA
// loop of the current chunk, so gather latency hides under ~6k cycles of HMMA.
// bf16 split precision: acc += Ah*Bh + Ah*Bl + Al*Bh (fp32 accum), rel err ~1e-5.

#define T_SMALL  0.05f
#define MAX_E    600064
__device__ float g_raw[MAX_E];

#define THREADS   512
#define XS_STRIDE 136   // bf16 per X row (128 + 8 pad) -> 272B rows, ldmatrix conflict-free
#define WS_STRIDE 264   // bf16 per W row (256 + 8 pad) -> 528B rows, conflict-free

// smem byte offsets
#define SM_XH    0                              // 128*136*2 = 34816
#define SM_XL    34816                          // 34816
#define SM_WH    69632                          // 128*264*2 = 67584
#define SM_WL    137216                         // 67584
#define SM_B1    204800                         // 512
#define SM_W2    205312                         // 512
#define SM_TOTAL 205824

__device__ __forceinline__ uint32_t smem_u32(const void* p) {
    uint32_t a;
    asm("{ .reg .u64 t; cvta.to.shared.u64 t, %1; cvt.u32.u64 %0, t; }" : "=r"(a) : "l"(p));
    return a;
}
__device__ __forceinline__ void ldmx4(uint32_t* r, uint32_t addr) {
    asm volatile("ldmatrix.sync.aligned.m8n8.x4.shared.b16 {%0,%1,%2,%3}, [%4];"
                 : "=r"(r[0]), "=r"(r[1]), "=r"(r[2]), "=r"(r[3]) : "r"(addr));
}
__device__ __forceinline__ void mma16816(float* c, const uint32_t* a, const uint32_t* b) {
    asm volatile("mma.sync.aligned.m16n8k16.row.col.f32.bf16.bf16.f32 "
                 "{%0,%1,%2,%3}, {%4,%5,%6,%7}, {%8,%9}, {%0,%1,%2,%3};"
                 : "+f"(c[0]), "+f"(c[1]), "+f"(c[2]), "+f"(c[3])
                 : "r"(a[0]), "r"(a[1]), "r"(a[2]), "r"(a[3]), "r"(b[0]), "r"(b[1]));
}
__device__ __forceinline__ uint32_t pk(__nv_bfloat162 v) { return *reinterpret_cast<uint32_t*>(&v); }

__global__ __launch_bounds__(THREADS, 1)
void edge_mlp_hmma(const float* __restrict__ emb,
                   const int*   __restrict__ eidx,
                   const float* __restrict__ W1,
                   const float* __restrict__ b1,
                   const float* __restrict__ W2,
                   int E, int ntiles)
{
    extern __shared__ char smem[];
    const uint32_t sbase = smem_u32(smem);

    __nv_bfloat16* xh  = reinterpret_cast<__nv_bfloat16*>(smem + SM_XH);
    __nv_bfloat16* xl  = reinterpret_cast<__nv_bfloat16*>(smem + SM_XL);
    __nv_bfloat16* wh  = reinterpret_cast<__nv_bfloat16*>(smem + SM_WH);
    __nv_bfloat16* wl  = reinterpret_cast<__nv_bfloat16*>(smem + SM_WL);
    float* b1s = reinterpret_cast<float*>(smem + SM_B1);
    float* w2s = reinterpret_cast<float*>(smem + SM_W2);

    const int t    = threadIdx.x;
    const int lane = t & 31;
    const int wid  = t >> 5;
    const int wm   = wid & 3;     // M block: rows wm*32 .. +31
    const int wn   = wid >> 2;    // N block: cols wn*32 .. +31

    const int halfId   = blockIdx.x & 1;
    const int group    = blockIdx.x >> 1;       // 0..73
    const int halfBase = halfId * 128;

    // gather mapping: 4 threads per row, 32 consecutive dims each
    const int qtr  = t & 3;
    const int grow = t >> 2;      // 0..127

    if (t < 128) { b1s[t] = b1[halfBase + t]; w2s[t] = W2[halfBase + t]; }

    // ---- resident W1^T half, hi/lo split: wh/wl[n][k] ----
    #pragma unroll 4
    for (int i = 0; i < 64; ++i) {
        int idx = t + THREADS * i;     // 0..32767
        int k = idx >> 7;              // 0..255  (coalesced over n)
        int n = idx & 127;
        float w = W1[k * 256 + halfBase + n];
        __nv_bfloat16 h = __float2bfloat16_rn(w);
        __nv_bfloat16 l = __float2bfloat16_rn(w - __bfloat162float(h));
        wh[n * WS_STRIDE + k] = h;
        wl[n * WS_STRIDE + k] = l;
    }

    float4 P[8];                       // prefetched gather data (32 floats)

    // prefetch (tile pt, side pc) into P
    auto prefetch = [&](int pt, int pc) {
        int e = pt * 128 + grow;
        if (e >= E) e = E - 1;
        int node = eidx[pc * E + e];
        const float4* src = reinterpret_cast<const float4*>(emb + (size_t)node * 128 + qtr * 32);
        #pragma unroll
        for (int q = 0; q < 8; ++q) P[q] = src[q];
    };
    // convert P -> xh/xl
    auto sts = [&]() {
        __nv_bfloat16* dh = xh + grow * XS_STRIDE + qtr * 32;
        __nv_bfloat16* dl = xl + grow * XS_STRIDE + qtr * 32;
        #pragma unroll
        for (int q = 0; q < 8; ++q) {
            float4 v = P[q];
            __nv_bfloat162 h01 = __floats2bfloat162_rn(v.x, v.y);
            __nv_bfloat162 h23 = __floats2bfloat162_rn(v.z, v.w);
            __nv_bfloat162 l01 = __floats2bfloat162_rn(v.x - __bfloat162float(h01.x),
                                                       v.y - __bfloat162float(h01.y));
            __nv_bfloat162 l23 = __floats2bfloat162_rn(v.z - __bfloat162float(h23.x),
                                                       v.w - __bfloat162float(h23.y));
            *reinterpret_cast<uint2*>(dh + q * 4) = make_uint2(pk(h01), pk(h23));
            *reinterpret_cast<uint2*>(dl + q * 4) = make_uint2(pk(l01), pk(l23));
        }
    };

    prefetch(group, 0);                // warm the pipeline (overlaps W staging below)
    __syncthreads();                   // W resident & b1/w2 ready

    for (int tile = group; tile < ntiles; tile += 74) {
        float acc[2][4][4];
        #pragma unroll
        for (int mi = 0; mi < 2; ++mi)
            #pragma unroll
            for (int nf = 0; nf < 4; ++nf)
                #pragma unroll
                for (int p = 0; p < 4; ++p) acc[mi][nf][p] = 0.0f;

        #pragma unroll
        for (int chunk = 0; chunk < 2; ++chunk) {
            __syncthreads();           // X buffer free (previous chunk's MMAs done)
            sts();
            __syncthreads();           // X ready

            // issue next prefetch before MMA (latency hides under HMMAs)
            if (chunk == 0) prefetch(tile, 1);
            else {
                int nt = tile + 74;
                prefetch(nt < ntiles ? nt : tile, 0);
            }

            // ---- 8 ksteps of m16n8k16 over this chunk ----
            #pragma unroll
            for (int ks = 0; ks < 8; ++ks) {
                const int kl = ks * 16;            // local k in X
                const int kg = chunk * 128 + kl;   // global k in W

                uint32_t Ah[2][4], Al[2][4];
                #pragma unroll
                for (int mi = 0; mi < 2; ++mi) {
                    int row  = wm * 32 + mi * 16 + (lane & 15);
                    int koff = kl + ((lane >> 4) << 3);
                    uint32_t a = sbase + SM_XH + (uint32_t)(row * XS_STRIDE + koff) * 2;
                    ldmx4(Ah[mi], a);
                    ldmx4(Al[mi], a + (SM_XL - SM_XH));
                }
                uint32_t Bh[4][2], Bl[4][2];
                #pragma unroll
                for (int ng = 0; ng < 2; ++ng) {
                    int nrow = wn * 32 + ng * 16 + (lane & 15);
                    int koff = kg + ((lane >> 4) << 3);
                    uint32_t a = sbase + SM_WH + (uint32_t)(nrow * WS_STRIDE + koff) * 2;
                    uint32_t r4[4];
                    ldmx4(r4, a);
                    Bh[2*ng][0] = r4[0]; Bh[2*ng+1][0] = r4[1];
                    Bh[2*ng][1] = r4[2]; Bh[2*ng+1][1] = r4[3];
                    ldmx4(r4, a + (SM_WL - SM_WH));
                    Bl[2*ng][0] = r4[0]; Bl[2*ng+1][0] = r4[1];
                    Bl[2*ng][1] = r4[2]; Bl[2*ng+1][1] = r4[3];
                }
                #pragma unroll
                for (int mi = 0; mi < 2; ++mi)
                    #pragma unroll
                    for (int nf = 0; nf < 4; ++nf) {
                        mma16816(acc[mi][nf], Ah[mi], Bh[nf]);
                        mma16816(acc[mi][nf], Ah[mi], Bl[nf]);
                        mma16816(acc[mi][nf], Al[mi], Bh[nf]);
                    }
            }
        }

        // ---- epilogue: relu(+b1) dot W2 over this warp's 32 cols ----
        #pragma unroll
        for (int mi = 0; mi < 2; ++mi) {
            float p0 = 0.0f, p1 = 0.0f;
            #pragma unroll
            for (int nf = 0; nf < 4; ++nf) {
                int c0 = wn * 32 + nf * 8 + 2 * (lane & 3);
                float bi0 = b1s[c0], bi1 = b1s[c0 + 1];
                float wv0 = w2s[c0], wv1 = w2s[c0 + 1];
                p0 = fmaf(fmaxf(acc[mi][nf][0] + bi0, 0.0f), wv0, p0);
                p0 = fmaf(fmaxf(acc[mi][nf][1] + bi1, 0.0f), wv1, p0);
                p1 = fmaf(fmaxf(acc[mi][nf][2] + bi0, 0.0f), wv0, p1);
                p1 = fmaf(fmaxf(acc[mi][nf][3] + bi1, 0.0f), wv1, p1);
            }
            p0 += __shfl_xor_sync(0xffffffffu, p0, 1);
            p0 += __shfl_xor_sync(0xffffffffu, p0, 2);
            p1 += __shfl_xor_sync(0xffffffffu, p1, 1);
            p1 += __shfl_xor_sync(0xffffffffu, p1, 2);
            if ((lane & 3) == 0) {
                int r0 = wm * 32 + mi * 16 + (lane >> 2);
                int e0 = tile * 128 + r0;
                if (e0 < E) atomicAdd(&g_raw[e0], p0);
                if (e0 + 8 < E) atomicAdd(&g_raw[e0 + 8], p1);
            }
        }
    }
}

__global__ void zero_raw(int E) {
    int i = blockIdx.x * blockDim.x + threadIdx.x;
    if (i < E) g_raw[i] = 0.0f;
}

__global__ void finalize(float* __restrict__ out, const float* __restrict__ b2, int E) {
    int i = blockIdx.x * blockDim.x + threadIdx.x;
    if (i < E) {
        float v = fmaxf(g_raw[i] + b2[0], 0.0f);
        out[i] = (v < T_SMALL) ? 0.0f : v;
    }
}

extern "C" void kernel_launch(void* const* d_in, const int* in_sizes, int n_in,
                              void* d_out, int out_size)
{
    const float* emb  = (const float*)d_in[0];
    const int*   eidx = (const int*)d_in[1];     // int32 (JAX x64 disabled)
    const float* W1   = (const float*)d_in[2];
    const float* b1   = (const float*)d_in[3];
    const float* W2   = (const float*)d_in[4];
    const float* b2   = (const float*)d_in[5];
    float*       out  = (float*)d_out;

    const int E = in_sizes[1] / 2;
    const int ntiles = (E + 127) / 128;

    cudaFuncSetAttribute(edge_mlp_hmma, cudaFuncAttributeMaxDynamicSharedMemorySize, SM_TOTAL);

    zero_raw<<<(E + 255) / 256, 256>>>(E);
    edge_mlp_hmma<<<148, THREADS, SM_TOTAL>>>(emb, eidx, W1, b1, W2, E, ntiles);
    finalize<<<(E + 255) / 256, 256>>>(out, b2, E);
}

// round 11
// speedup vs baseline: 8.4728x; 2.9241x over previous
#include <cuda_runtime.h>
#include <cuda_bf16.h>
#include <cstdint>

// LinkPredictorMLP, restructured:
//   UV[n] = emb[n] @ [W1_top | W1_bot]   (one dense GEMM over 100k nodes, bf16 split HMMA)
//   out[e] = thresh(relu( relu(U[row]+V[col]+b1) . W2 + b2 ))   (memory-bound edge pass)
// This cuts tensor FLOPs 6x vs the per-edge GEMM (100k node rows vs 1.2M edge rows).
//
// bf16 split precision in the GEMM: v = hi + lo; acc += Ah*Bh + Ah*Bl + Al*Bh (fp32).

#define T_SMALL  0.05f
#define NMAX     100096     // padded node count
#define HTOT     512        // U(256) | V(256)

__device__ __nv_bfloat16 g_Eh[(size_t)NMAX * 128];
__device__ __nv_bfloat16 g_El[(size_t)NMAX * 128];
__device__ __nv_bfloat16 g_Wh[HTOT * 128];
__device__ __nv_bfloat16 g_Wl[HTOT * 128];
__device__ float         g_uv[(size_t)NMAX * HTOT];

__device__ __forceinline__ uint32_t smem_u32(const void* p) {
    uint32_t a;
    asm("{ .reg .u64 t; cvta.to.shared.u64 t, %1; cvt.u32.u64 %0, t; }" : "=r"(a) : "l"(p));
    return a;
}
__device__ __forceinline__ void ldmx4(uint32_t* r, uint32_t addr) {
    asm volatile("ldmatrix.sync.aligned.m8n8.x4.shared.b16 {%0,%1,%2,%3}, [%4];"
                 : "=r"(r[0]), "=r"(r[1]), "=r"(r[2]), "=r"(r[3]) : "r"(addr));
}
__device__ __forceinline__ void mma16816(float* c, const uint32_t* a, const uint32_t* b) {
    asm volatile("mma.sync.aligned.m16n8k16.row.col.f32.bf16.bf16.f32 "
                 "{%0,%1,%2,%3}, {%4,%5,%6,%7}, {%8,%9}, {%0,%1,%2,%3};"
                 : "+f"(c[0]), "+f"(c[1]), "+f"(c[2]), "+f"(c[3])
                 : "r"(a[0]), "r"(a[1]), "r"(a[2]), "r"(a[3]), "r"(b[0]), "r"(b[1]));
}

// ---------------------------------------------------------------- prep kernels
// Split W1 into bf16 hi/lo planes laid out [n][k] (n = part*256 + h, k = 0..127).
__global__ void prep_w(const float* __restrict__ W1) {
    int i = blockIdx.x * blockDim.x + threadIdx.x;     // 0 .. 65535
    int k    = i >> 9;
    int part = (i >> 8) & 1;
    int h    = i & 255;
    int n    = part * 256 + h;
    float w = W1[(part * 128 + k) * 256 + h];
    __nv_bfloat16 hi = __float2bfloat16_rn(w);
    __nv_bfloat16 lo = __float2bfloat16_rn(w - __bfloat162float(hi));
    g_Wh[n * 128 + k] = hi;
    g_Wl[n * 128 + k] = lo;
}

// Split emb into bf16 hi/lo planes [n][k].
__global__ void prep_e(const float* __restrict__ emb, int Ntot) {
    int i = blockIdx.x * blockDim.x + threadIdx.x;     // float4 granularity
    int r = i >> 5, c = i & 31;
    if (r >= Ntot) return;
    float4 v = reinterpret_cast<const float4*>(emb)[(size_t)r * 32 + c];
    __nv_bfloat16 h0 = __float2bfloat16_rn(v.x), h1 = __float2bfloat16_rn(v.y);
    __nv_bfloat16 h2 = __float2bfloat16_rn(v.z), h3 = __float2bfloat16_rn(v.w);
    __nv_bfloat16 l0 = __float2bfloat16_rn(v.x - __bfloat162float(h0));
    __nv_bfloat16 l1 = __float2bfloat16_rn(v.y - __bfloat162float(h1));
    __nv_bfloat16 l2 = __float2bfloat16_rn(v.z - __bfloat162float(h2));
    __nv_bfloat16 l3 = __float2bfloat16_rn(v.w - __bfloat162float(h3));
    __nv_bfloat162* dh = reinterpret_cast<__nv_bfloat162*>(g_Eh + (size_t)r * 128 + c * 4);
    __nv_bfloat162* dl = reinterpret_cast<__nv_bfloat162*>(g_El + (size_t)r * 128 + c * 4);
    dh[0] = __nv_bfloat162{h0, h1}; dh[1] = __nv_bfloat162{h2, h3};
    dl[0] = __nv_bfloat162{l0, l1}; dl[1] = __nv_bfloat162{l2, l3};
}

// ---------------------------------------------------------------- UV GEMM
// C[128x128 tile] = Eh/El[m-tile] x Wh/Wl[n-tile], K=128, 512 thr (16 warps, 4Mx4N).
#define GSTRIDE 136      // bf16 per smem row (128 + 8 pad), conflict-free ldmatrix
#define SA_H 0
#define SA_L 34816
#define SB_H 69632
#define SB_L 104448
#define SG_TOTAL 139264

__global__ __launch_bounds__(512, 1)
void gemm_uv(int Mtot)
{
    extern __shared__ char smem[];
    const uint32_t sbase = smem_u32(smem);

    const int t    = threadIdx.x;
    const int lane = t & 31;
    const int wid  = t >> 5;
    const int wm   = wid & 3;      // M: rows wm*32..+31
    const int wn   = wid >> 2;     // N: cols wn*32..+31

    const int mtile = blockIdx.x >> 2;
    const int n0    = (blockIdx.x & 3) * 128;
    const int m0    = mtile * 128;

    // stage A planes (Eh/El rows m0..m0+127) and B planes (Wh/Wl rows n0..n0+127)
    #pragma unroll
    for (int it = 0; it < 8; ++it) {                 // A: 4096 uint4
        int idx = t + 512 * it;
        int pl = idx >> 11;                          // 0=hi, 1=lo
        int r  = (idx >> 4) & 127;
        int kc = idx & 15;
        int row = m0 + r; if (row >= Mtot) row = Mtot - 1;
        const uint4* src = reinterpret_cast<const uint4*>(
            (pl ? g_El : g_Eh) + (size_t)row * 128 + kc * 8);
        char* dst = smem + (pl ? SA_L : SA_H) + (r * GSTRIDE + kc * 8) * 2;
        *reinterpret_cast<uint4*>(dst) = *src;
    }
    #pragma unroll
    for (int it = 0; it < 8; ++it) {                 // B: 4096 uint4
        int idx = t + 512 * it;
        int pl = idx >> 11;
        int r  = (idx >> 4) & 127;
        int kc = idx & 15;
        const uint4* src = reinterpret_cast<const uint4*>(
            (pl ? g_Wl : g_Wh) + (size_t)(n0 + r) * 128 + kc * 8);
        char* dst = smem + (pl ? SB_L : SB_H) + (r * GSTRIDE + kc * 8) * 2;
        *reinterpret_cast<uint4*>(dst) = *src;
    }
    __syncthreads();

    float acc[2][4][4];
    #pragma unroll
    for (int mi = 0; mi < 2; ++mi)
        #pragma unroll
        for (int nf = 0; nf < 4; ++nf)
            #pragma unroll
            for (int p = 0; p < 4; ++p) acc[mi][nf][p] = 0.0f;

    #pragma unroll
    for (int ks = 0; ks < 8; ++ks) {
        const int kl = ks * 16;
        uint32_t Ah[2][4], Al[2][4];
        #pragma unroll
        for (int mi = 0; mi < 2; ++mi) {
            int row  = wm * 32 + mi * 16 + (lane & 15);
            int koff = kl + ((lane >> 4) << 3);
            uint32_t a = sbase + SA_H + (uint32_t)(row * GSTRIDE + koff) * 2;
            ldmx4(Ah[mi], a);
            ldmx4(Al[mi], a + (SA_L - SA_H));
        }
        uint32_t Bh[4][2], Bl[4][2];
        #pragma unroll
        for (int ng = 0; ng < 2; ++ng) {
            int nrow = wn * 32 + ng * 16 + (lane & 15);
            int koff = kl + ((lane >> 4) << 3);
            uint32_t a = sbase + SB_H + (uint32_t)(nrow * GSTRIDE + koff) * 2;
            uint32_t r4[4];
            ldmx4(r4, a);
            Bh[2*ng][0] = r4[0]; Bh[2*ng+1][0] = r4[1];
            Bh[2*ng][1] = r4[2]; Bh[2*ng+1][1] = r4[3];
            ldmx4(r4, a + (SB_L - SB_H));
            Bl[2*ng][0] = r4[0]; Bl[2*ng+1][0] = r4[1];
            Bl[2*ng][1] = r4[2]; Bl[2*ng+1][1] = r4[3];
        }
        #pragma unroll
        for (int mi = 0; mi < 2; ++mi)
            #pragma unroll
            for (int nf = 0; nf < 4; ++nf) {
                mma16816(acc[mi][nf], Ah[mi], Bh[nf]);
                mma16816(acc[mi][nf], Ah[mi], Bl[nf]);
                mma16816(acc[mi][nf], Al[mi], Bh[nf]);
            }
    }

    // store: c0,c1 -> row (lane>>2), cols 2*(lane&3)+{0,1}; c2,c3 -> row+8
    #pragma unroll
    for (int mi = 0; mi < 2; ++mi) {
        int rbase = m0 + wm * 32 + mi * 16 + (lane >> 2);
        #pragma unroll
        for (int nf = 0; nf < 4; ++nf) {
            int n = n0 + wn * 32 + nf * 8 + 2 * (lane & 3);
            if (rbase < Mtot)
                *reinterpret_cast<float2*>(&g_uv[(size_t)rbase * HTOT + n]) =
                    make_float2(acc[mi][nf][0], acc[mi][nf][1]);
            if (rbase + 8 < Mtot)
                *reinterpret_cast<float2*>(&g_uv[(size_t)(rbase + 8) * HTOT + n]) =
                    make_float2(acc[mi][nf][2], acc[mi][nf][3]);
        }
    }
}

// ---------------------------------------------------------------- edge pass
// 4 edges per warp, 8 lanes per edge; fully-coalesced 128B segments of U/V rows.
__global__ __launch_bounds__(256)
void edge_eval(const int* __restrict__ eidx,
               const float* __restrict__ b1,
               const float* __restrict__ W2,
               const float* __restrict__ b2,
               float* __restrict__ out, int E)
{
    __shared__ float b1s[256], w2s[256];
    int t = threadIdx.x;
    if (t < 256) { b1s[t] = b1[t]; w2s[t] = W2[t]; }
    __syncthreads();

    const int lane = t & 31;
    const int sub  = lane >> 3;          // edge within warp
    const int sl   = lane & 7;           // lane within edge
    const int warp = (blockIdx.x * 256 + t) >> 5;

    int e = warp * 4 + sub;
    int ec = e < E ? e : E - 1;
    const int row = eidx[ec];
    const int col = eidx[E + ec];
    const float* up = g_uv + (size_t)row * HTOT;
    const float* vp = g_uv + (size_t)col * HTOT + 256;

    float acc = 0.0f;
    #pragma unroll
    for (int it = 0; it < 8; ++it) {
        int j = it * 32 + sl * 4;
        float4 u = *reinterpret_cast<const float4*>(up + j);
        float4 v = *reinterpret_cast<const float4*>(vp + j);
        float4 bb = *reinterpret_cast<const float4*>(b1s + j);
        float4 ww = *reinterpret_cast<const float4*>(w2s + j);
        acc = fmaf(fmaxf(u.x + v.x + bb.x, 0.0f), ww.x, acc);
        acc = fmaf(fmaxf(u.y + v.y + bb.y, 0.0f), ww.y, acc);
        acc = fmaf(fmaxf(u.z + v.z + bb.z, 0.0f), ww.z, acc);
        acc = fmaf(fmaxf(u.w + v.w + bb.w, 0.0f), ww.w, acc);
    }
    acc += __shfl_xor_sync(0xffffffffu, acc, 1);
    acc += __shfl_xor_sync(0xffffffffu, acc, 2);
    acc += __shfl_xor_sync(0xffffffffu, acc, 4);

    if (sl == 0 && e < E) {
        float v = fmaxf(acc + b2[0], 0.0f);
        out[e] = (v < T_SMALL) ? 0.0f : v;
    }
}

extern "C" void kernel_launch(void* const* d_in, const int* in_sizes, int n_in,
                              void* d_out, int out_size)
{
    const float* emb  = (const float*)d_in[0];
    const int*   eidx = (const int*)d_in[1];     // int32 (JAX x64 disabled)
    const float* W1   = (const float*)d_in[2];
    const float* b1   = (const float*)d_in[3];
    const float* W2   = (const float*)d_in[4];
    const float* b2   = (const float*)d_in[5];
    float*       out  = (float*)d_out;

    const int E    = in_sizes[1] / 2;
    const int Ntot = in_sizes[0] / 128;          // node count
    const int mtiles = (Ntot + 127) / 128;

    cudaFuncSetAttribute(gemm_uv, cudaFuncAttributeMaxDynamicSharedMemorySize, SG_TOTAL);

    prep_w<<<256, 256>>>(W1);
    prep_e<<<(Ntot * 32 + 255) / 256, 256>>>(emb, Ntot);
    gemm_uv<<<mtiles * 4, 512, SG_TOTAL>>>(Ntot);
    edge_eval<<<(E + 31) / 32, 256>>>(eidx, b1, W2, b2, out, E);
}